// round 6
// baseline (speedup 1.0000x reference)
#include <cuda_runtime.h>
#include <math.h>

// Learned optimizer step. Inputs (metadata order):
// 0 grad[N] 1 state0[N] 2 state1[N] 3 loss_cur[1] 4 loss_old[1] 5 iteration[1]
// 6 gradient_param[N] 7 extrapolation[N]
// 8 cw0[20x4] 9 cb0[20] 10 cw1[20x20] 11 cb1[20] 12 cw2[20x20] 13 cb2[20]
// 14 cw3[1x20] 15 cb3[1]
// 16 lw0[30x6] 17 lb0[30] 18 lw1[20x30] 19 lb1[20] 20 lw2[10x20] 21 lb2[10]
// 22 lw3[4x10] 23 lb3[4]
// Output: float32 [N]
//
// Zero-stack discipline: no inline asm, no 64-bit packed math, no local
// arrays anywhere; all per-thread state is named float scalars.
// Main-kernel structure: half-layer (10-output) accumulation, 2 elements
// per thread, weights staged in shared as 12-float padded rows (3 aligned
// LDS.128 per row feeding 20 FFMAs).

#define RED_BLOCKS 1024
#define RED_THREADS 256
#define MAIN_THREADS 128
#define MAIN_BLOCKS 8192

__device__ float4 g_part[RED_BLOCKS];
__device__ unsigned int g_ticket = 0;
__device__ float g_coeff0, g_coeff1, g_coeff2, g_coeff3;
__device__ float g_inv_gn;
__device__ float g_inv_dn;
__device__ float g_fscale;

// ---------------------------------------------------------------------------
// Kernel A (fused): block partial reductions + last-block finalize
// (combine partials, features, tiny coefficient MLP). Deterministic:
// the single last block combines partials in fixed order.
// ---------------------------------------------------------------------------
__global__ void reduce_scalars_kernel(
    const float* __restrict__ grad, const float* __restrict__ s0,
    const float* __restrict__ s1, int n,
    const float* __restrict__ loss_cur, const float* __restrict__ loss_old,
    const int* __restrict__ iter_p,
    const float* __restrict__ lw0, const float* __restrict__ lb0,
    const float* __restrict__ lw1, const float* __restrict__ lb1,
    const float* __restrict__ lw2, const float* __restrict__ lb2,
    const float* __restrict__ lw3, const float* __restrict__ lb3) {
    __shared__ float4 sh[RED_THREADS / 32];
    __shared__ int s_last;
    __shared__ float sfeat[6];
    __shared__ float sh0[30];
    __shared__ float sh1[20];
    __shared__ float sh2[10];

    int tid = threadIdx.x;
    int n4 = n >> 2;
    float sg2 = 0.f, sd2 = 0.f, sgd = 0.f, amax = 0.f;
    for (int i = blockIdx.x * blockDim.x + tid; i < n4;
         i += gridDim.x * blockDim.x) {
        float4 g = ((const float4*)grad)[i];
        float4 a = ((const float4*)s0)[i];
        float4 b = ((const float4*)s1)[i];
        float dx = b.x - a.x, dy = b.y - a.y, dz = b.z - a.z, dw = b.w - a.w;
        sg2 += g.x * g.x + g.y * g.y + g.z * g.z + g.w * g.w;
        sd2 += dx * dx + dy * dy + dz * dz + dw * dw;
        sgd += g.x * dx + g.y * dy + g.z * dz + g.w * dw;
        amax = fmaxf(amax, fmaxf(fmaxf(fabsf(g.x), fabsf(g.y)),
                                 fmaxf(fabsf(g.z), fabsf(g.w))));
    }
    #pragma unroll
    for (int off = 16; off; off >>= 1) {
        sg2 += __shfl_down_sync(0xffffffffu, sg2, off);
        sd2 += __shfl_down_sync(0xffffffffu, sd2, off);
        sgd += __shfl_down_sync(0xffffffffu, sgd, off);
        amax = fmaxf(amax, __shfl_down_sync(0xffffffffu, amax, off));
    }
    int lane = tid & 31, w = tid >> 5;
    if (!lane) sh[w] = make_float4(sg2, sd2, sgd, amax);
    __syncthreads();
    if (tid == 0) {
        float4 v = sh[0];
        #pragma unroll
        for (int i = 1; i < RED_THREADS / 32; i++) {
            float4 q = sh[i];
            v.x += q.x; v.y += q.y; v.z += q.z; v.w = fmaxf(v.w, q.w);
        }
        g_part[blockIdx.x] = v;
        __threadfence();
        // self-resetting ticket: last arrival sees RED_BLOCKS-1, counter -> 0
        unsigned int old = atomicInc(&g_ticket, RED_BLOCKS - 1);
        s_last = (old == RED_BLOCKS - 1);
    }
    __syncthreads();
    if (!s_last) return;

    // ---- last block: combine 1024 partials (fixed order) ----
    sg2 = 0.f; sd2 = 0.f; sgd = 0.f; amax = 0.f;
    for (int i = tid; i < RED_BLOCKS; i += RED_THREADS) {
        float4 p = g_part[i];
        sg2 += p.x; sd2 += p.y; sgd += p.z; amax = fmaxf(amax, p.w);
    }
    #pragma unroll
    for (int off = 16; off; off >>= 1) {
        sg2 += __shfl_down_sync(0xffffffffu, sg2, off);
        sd2 += __shfl_down_sync(0xffffffffu, sd2, off);
        sgd += __shfl_down_sync(0xffffffffu, sgd, off);
        amax = fmaxf(amax, __shfl_down_sync(0xffffffffu, amax, off));
    }
    __syncthreads();  // sh reuse
    if (!lane) sh[w] = make_float4(sg2, sd2, sgd, amax);
    __syncthreads();

    if (tid == 0) {
        float4 v = sh[0];
        #pragma unroll
        for (int i = 1; i < RED_THREADS / 32; i++) {
            float4 q = sh[i];
            v.x += q.x; v.y += q.y; v.z += q.z; v.w = fmaxf(v.w, q.w);
        }
        float gn = sqrtf(v.x);
        float dn = sqrtf(v.y);
        float inv_gn = (gn > 1e-10f) ? (1.0f / gn) : 1.0f;
        float inv_dn = (dn > 1e-10f) ? (1.0f / dn) : 1.0f;
        float it = (float)iter_p[0];
        sfeat[0] = log1pf(gn);
        sfeat[1] = log1pf(dn);
        sfeat[2] = v.z * inv_gn * inv_dn;
        sfeat[3] = v.w * inv_gn;
        sfeat[4] = it;
        sfeat[5] = logf(loss_cur[0]) - logf(loss_old[0]);
        g_inv_gn = inv_gn;
        g_inv_dn = inv_dn;
        g_fscale = 1.0f / sqrtf(1.0f + it);
    }
    __syncthreads();

    if (tid < 30) {
        float a = lb0[tid];
        #pragma unroll
        for (int f = 0; f < 6; f++) a = fmaf(lw0[tid * 6 + f], sfeat[f], a);
        sh0[tid] = fmaxf(a, 0.0f);
    }
    __syncthreads();
    if (tid < 20) {
        float a = lb1[tid];
        #pragma unroll
        for (int c = 0; c < 30; c++) a = fmaf(lw1[tid * 30 + c], sh0[c], a);
        sh1[tid] = fmaxf(a, 0.0f);
    }
    __syncthreads();
    if (tid < 10) {
        float a = lb2[tid];
        #pragma unroll
        for (int c = 0; c < 20; c++) a = fmaf(lw2[tid * 20 + c], sh1[c], a);
        sh2[tid] = fmaxf(a, 0.0f);
    }
    __syncthreads();
    if (tid < 4) {
        float a = lb3[tid];
        #pragma unroll
        for (int c = 0; c < 10; c++) a = fmaf(lw3[tid * 10 + c], sh2[c], a);
        if (tid == 0) g_coeff0 = a;
        if (tid == 1) g_coeff1 = a;
        if (tid == 2) g_coeff2 = a;
        if (tid == 3) g_coeff3 = a;
    }
}

// ---------------------------------------------------------------------------
// Kernel B: per-element MLP 4->20->20->20->1, 2 elements/thread (u=.x, v=.y).
// Each 20-wide layer computed as two 10-output halves: only 10+10 accumulators
// live at a time. Weight rows padded to 12 floats (48B, 16B-aligned): one row
// = 3 LDS.128 feeding 20 FFMAs.
// ---------------------------------------------------------------------------

// au0..au9 / av0..av9 += row * {HU, HV}  (3 aligned quad loads, 20 FFMA)
#define ACC2H(ROWPTR, HU, HV) { \
    const float4* r_ = (const float4*)(ROWPTR); \
    float4 q0 = r_[0], q1 = r_[1], q2 = r_[2]; \
    au0 = fmaf(q0.x, (HU), au0); av0 = fmaf(q0.x, (HV), av0); \
    au1 = fmaf(q0.y, (HU), au1); av1 = fmaf(q0.y, (HV), av1); \
    au2 = fmaf(q0.z, (HU), au2); av2 = fmaf(q0.z, (HV), av2); \
    au3 = fmaf(q0.w, (HU), au3); av3 = fmaf(q0.w, (HV), av3); \
    au4 = fmaf(q1.x, (HU), au4); av4 = fmaf(q1.x, (HV), av4); \
    au5 = fmaf(q1.y, (HU), au5); av5 = fmaf(q1.y, (HV), av5); \
    au6 = fmaf(q1.z, (HU), au6); av6 = fmaf(q1.z, (HV), av6); \
    au7 = fmaf(q1.w, (HU), au7); av7 = fmaf(q1.w, (HV), av7); \
    au8 = fmaf(q2.x, (HU), au8); av8 = fmaf(q2.x, (HV), av8); \
    au9 = fmaf(q2.y, (HU), au9); av9 = fmaf(q2.y, (HV), av9); }

#define BIASH(SB) { \
    const float4* b_ = (const float4*)(SB); \
    float4 q0 = b_[0], q1 = b_[1], q2 = b_[2]; \
    au0 = q0.x; au1 = q0.y; au2 = q0.z; au3 = q0.w; \
    au4 = q1.x; au5 = q1.y; au6 = q1.z; au7 = q1.w; \
    au8 = q2.x; au9 = q2.y; \
    av0 = au0; av1 = au1; av2 = au2; av3 = au3; av4 = au4; \
    av5 = au5; av6 = au6; av7 = au7; av8 = au8; av9 = au9; }

// P##u0..9 / P##v0..9 = relu(acc)
#define RELU_A(P) \
    P##u0 = fmaxf(au0, 0.f); P##u1 = fmaxf(au1, 0.f); P##u2 = fmaxf(au2, 0.f); \
    P##u3 = fmaxf(au3, 0.f); P##u4 = fmaxf(au4, 0.f); P##u5 = fmaxf(au5, 0.f); \
    P##u6 = fmaxf(au6, 0.f); P##u7 = fmaxf(au7, 0.f); P##u8 = fmaxf(au8, 0.f); \
    P##u9 = fmaxf(au9, 0.f); \
    P##v0 = fmaxf(av0, 0.f); P##v1 = fmaxf(av1, 0.f); P##v2 = fmaxf(av2, 0.f); \
    P##v3 = fmaxf(av3, 0.f); P##v4 = fmaxf(av4, 0.f); P##v5 = fmaxf(av5, 0.f); \
    P##v6 = fmaxf(av6, 0.f); P##v7 = fmaxf(av7, 0.f); P##v8 = fmaxf(av8, 0.f); \
    P##v9 = fmaxf(av9, 0.f);

// P##u10..19 / P##v10..19 = relu(acc)
#define RELU_B(P) \
    P##u10 = fmaxf(au0, 0.f); P##u11 = fmaxf(au1, 0.f); P##u12 = fmaxf(au2, 0.f); \
    P##u13 = fmaxf(au3, 0.f); P##u14 = fmaxf(au4, 0.f); P##u15 = fmaxf(au5, 0.f); \
    P##u16 = fmaxf(au6, 0.f); P##u17 = fmaxf(au7, 0.f); P##u18 = fmaxf(au8, 0.f); \
    P##u19 = fmaxf(au9, 0.f); \
    P##v10 = fmaxf(av0, 0.f); P##v11 = fmaxf(av1, 0.f); P##v12 = fmaxf(av2, 0.f); \
    P##v13 = fmaxf(av3, 0.f); P##v14 = fmaxf(av4, 0.f); P##v15 = fmaxf(av5, 0.f); \
    P##v16 = fmaxf(av6, 0.f); P##v17 = fmaxf(av7, 0.f); P##v18 = fmaxf(av8, 0.f); \
    P##v19 = fmaxf(av9, 0.f);

// one half of a 20->20 layer: 20 input channels into 10 outputs
#define HALF20(SW, SB, IP) \
    BIASH(SB) \
    ACC2H(&(SW)[0][0],  IP##u0,  IP##v0)  ACC2H(&(SW)[1][0],  IP##u1,  IP##v1) \
    ACC2H(&(SW)[2][0],  IP##u2,  IP##v2)  ACC2H(&(SW)[3][0],  IP##u3,  IP##v3) \
    ACC2H(&(SW)[4][0],  IP##u4,  IP##v4)  ACC2H(&(SW)[5][0],  IP##u5,  IP##v5) \
    ACC2H(&(SW)[6][0],  IP##u6,  IP##v6)  ACC2H(&(SW)[7][0],  IP##u7,  IP##v7) \
    ACC2H(&(SW)[8][0],  IP##u8,  IP##v8)  ACC2H(&(SW)[9][0],  IP##u9,  IP##v9) \
    ACC2H(&(SW)[10][0], IP##u10, IP##v10) ACC2H(&(SW)[11][0], IP##u11, IP##v11) \
    ACC2H(&(SW)[12][0], IP##u12, IP##v12) ACC2H(&(SW)[13][0], IP##u13, IP##v13) \
    ACC2H(&(SW)[14][0], IP##u14, IP##v14) ACC2H(&(SW)[15][0], IP##u15, IP##v15) \
    ACC2H(&(SW)[16][0], IP##u16, IP##v16) ACC2H(&(SW)[17][0], IP##u17, IP##v17) \
    ACC2H(&(SW)[18][0], IP##u18, IP##v18) ACC2H(&(SW)[19][0], IP##u19, IP##v19)

#define DECL20(P) \
    float P##u0, P##u1, P##u2, P##u3, P##u4, P##u5, P##u6, P##u7, P##u8, P##u9, \
          P##u10, P##u11, P##u12, P##u13, P##u14, P##u15, P##u16, P##u17, P##u18, P##u19; \
    float P##v0, P##v1, P##v2, P##v3, P##v4, P##v5, P##v6, P##v7, P##v8, P##v9, \
          P##v10, P##v11, P##v12, P##v13, P##v14, P##v15, P##v16, P##v17, P##v18, P##v19;

__global__ void __launch_bounds__(MAIN_THREADS) main_kernel(
    const float* __restrict__ grad, const float* __restrict__ s0,
    const float* __restrict__ s1, const float* __restrict__ gp,
    const float* __restrict__ ex,
    const float* __restrict__ cw0, const float* __restrict__ cb0,
    const float* __restrict__ cw1, const float* __restrict__ cb1,
    const float* __restrict__ cw2, const float* __restrict__ cb2,
    const float* __restrict__ cw3, const float* __restrict__ cb3,
    float* __restrict__ out, int n) {
    // half-layer weight tiles: row = input channel, 12 floats padded (48B)
    __shared__ __align__(16) float sw0a[4][12],  sw0b[4][12];
    __shared__ __align__(16) float sw1a[20][12], sw1b[20][12];
    __shared__ __align__(16) float sw2a[20][12], sw2b[20][12];
    __shared__ __align__(16) float sw3[20];
    __shared__ __align__(16) float sb0a[12], sb0b[12];
    __shared__ __align__(16) float sb1a[12], sb1b[12];
    __shared__ __align__(16) float sb2a[12], sb2b[12];
    __shared__ float sb3f;

    int tid = threadIdx.x;

    float c0 = g_coeff0, c1 = g_coeff1, c2 = g_coeff2, c3 = g_coeff3;
    float inv_gn = g_inv_gn, inv_dn = g_inv_dn, fscale = g_fscale;

    // ---- stage weights (transposed, halved, padded; coeff/fscale folded) ----
    if (tid < 48) {
        int c = tid / 12, j = tid % 12;
        float cf = (c == 0) ? c0 : (c == 1) ? c1 : (c == 2) ? c2 : c3;
        sw0a[c][j] = (j < 10) ? cw0[j * 4 + c] * cf : 0.f;
        sw0b[c][j] = (j < 10) ? cw0[(j + 10) * 4 + c] * cf : 0.f;
    }
    for (int k = tid; k < 240; k += MAIN_THREADS) {
        int c = k / 12, j = k % 12;
        sw1a[c][j] = (j < 10) ? cw1[j * 20 + c] : 0.f;
        sw1b[c][j] = (j < 10) ? cw1[(j + 10) * 20 + c] : 0.f;
        sw2a[c][j] = (j < 10) ? cw2[j * 20 + c] : 0.f;
        sw2b[c][j] = (j < 10) ? cw2[(j + 10) * 20 + c] : 0.f;
    }
    if (tid < 12) {
        sb0a[tid] = (tid < 10) ? cb0[tid] : 0.f;
        sb0b[tid] = (tid < 10) ? cb0[tid + 10] : 0.f;
        sb1a[tid] = (tid < 10) ? cb1[tid] : 0.f;
        sb1b[tid] = (tid < 10) ? cb1[tid + 10] : 0.f;
        sb2a[tid] = (tid < 10) ? cb2[tid] : 0.f;
        sb2b[tid] = (tid < 10) ? cb2[tid + 10] : 0.f;
    }
    if (tid < 20) sw3[tid] = cw3[tid] * fscale;
    if (tid == 0) sb3f = cb3[0] * fscale;
    __syncthreads();

    int npair = n >> 1;
    int stride = gridDim.x * MAIN_THREADS;
    for (int p = blockIdx.x * MAIN_THREADS + tid; p < npair; p += stride) {
        float2 g2 = ((const float2*)grad)[p];
        float2 a2 = ((const float2*)s0)[p];
        float2 b2 = ((const float2*)s1)[p];
        float2 p2 = ((const float2*)gp)[p];
        float2 e2 = ((const float2*)ex)[p];

        float gxu = g2.x * inv_gn, gxv = g2.y * inv_gn;
        float dxu = (b2.x - a2.x) * inv_dn, dxv = (b2.y - a2.y) * inv_dn;
        float t0u = p2.x * gxu, t0v = p2.y * gxv;  // gradient_param * g
        float t1u = e2.x * dxu, t1v = e2.y * dxv;  // extrapolation * d

        float au0, au1, au2, au3, au4, au5, au6, au7, au8, au9;
        float av0, av1, av2, av3, av4, av5, av6, av7, av8, av9;
        DECL20(h)
        DECL20(g)

        // ---- layer 0: 4 -> 20 (two halves) ----
        BIASH(sb0a)
        ACC2H(&sw0a[0][0], t0u, t0v) ACC2H(&sw0a[1][0], t1u, t1v)
        ACC2H(&sw0a[2][0], gxu, gxv) ACC2H(&sw0a[3][0], dxu, dxv)
        RELU_A(h)
        BIASH(sb0b)
        ACC2H(&sw0b[0][0], t0u, t0v) ACC2H(&sw0b[1][0], t1u, t1v)
        ACC2H(&sw0b[2][0], gxu, gxv) ACC2H(&sw0b[3][0], dxu, dxv)
        RELU_B(h)

        // ---- layer 1: 20 -> 20 (h -> g) ----
        HALF20(sw1a, sb1a, h)
        RELU_A(g)
        HALF20(sw1b, sb1b, h)
        RELU_B(g)

        // ---- layer 2: 20 -> 20 (g -> h) ----
        HALF20(sw2a, sb2a, g)
        RELU_A(h)
        HALF20(sw2b, sb2b, g)
        RELU_B(h)

        // ---- layer 3: 20 -> 1 (fscale folded) ----
        float accu = sb3f, accv = sb3f;
        {
            const float4* r_ = (const float4*)sw3;
            float4 q0 = r_[0], q1 = r_[1], q2 = r_[2], q3 = r_[3], q4 = r_[4];
            accu = fmaf(q0.x, hu0, accu);  accv = fmaf(q0.x, hv0, accv);
            accu = fmaf(q0.y, hu1, accu);  accv = fmaf(q0.y, hv1, accv);
            accu = fmaf(q0.z, hu2, accu);  accv = fmaf(q0.z, hv2, accv);
            accu = fmaf(q0.w, hu3, accu);  accv = fmaf(q0.w, hv3, accv);
            accu = fmaf(q1.x, hu4, accu);  accv = fmaf(q1.x, hv4, accv);
            accu = fmaf(q1.y, hu5, accu);  accv = fmaf(q1.y, hv5, accv);
            accu = fmaf(q1.z, hu6, accu);  accv = fmaf(q1.z, hv6, accv);
            accu = fmaf(q1.w, hu7, accu);  accv = fmaf(q1.w, hv7, accv);
            accu = fmaf(q2.x, hu8, accu);  accv = fmaf(q2.x, hv8, accv);
            accu = fmaf(q2.y, hu9, accu);  accv = fmaf(q2.y, hv9, accv);
            accu = fmaf(q2.z, hu10, accu); accv = fmaf(q2.z, hv10, accv);
            accu = fmaf(q2.w, hu11, accu); accv = fmaf(q2.w, hv11, accv);
            accu = fmaf(q3.x, hu12, accu); accv = fmaf(q3.x, hv12, accv);
            accu = fmaf(q3.y, hu13, accu); accv = fmaf(q3.y, hv13, accv);
            accu = fmaf(q3.z, hu14, accu); accv = fmaf(q3.z, hv14, accv);
            accu = fmaf(q3.w, hu15, accu); accv = fmaf(q3.w, hv15, accv);
            accu = fmaf(q4.x, hu16, accu); accv = fmaf(q4.x, hv16, accv);
            accu = fmaf(q4.y, hu17, accu); accv = fmaf(q4.y, hv17, accv);
            accu = fmaf(q4.z, hu18, accu); accv = fmaf(q4.z, hv18, accv);
            accu = fmaf(q4.w, hu19, accu); accv = fmaf(q4.w, hv19, accv);
        }
        float2 o2;
        o2.x = b2.x + accu;
        o2.y = b2.y + accv;
        ((float2*)out)[p] = o2;
    }
}

// ---------------------------------------------------------------------------
extern "C" void kernel_launch(void* const* d_in, const int* in_sizes, int n_in,
                              void* d_out, int out_size) {
    const float* grad = (const float*)d_in[0];
    const float* s0   = (const float*)d_in[1];
    const float* s1   = (const float*)d_in[2];
    const float* loss_cur = (const float*)d_in[3];
    const float* loss_old = (const float*)d_in[4];
    const int*   iter_p   = (const int*)d_in[5];
    const float* gp = (const float*)d_in[6];
    const float* ex = (const float*)d_in[7];
    const float* cw0 = (const float*)d_in[8];
    const float* cb0 = (const float*)d_in[9];
    const float* cw1 = (const float*)d_in[10];
    const float* cb1 = (const float*)d_in[11];
    const float* cw2 = (const float*)d_in[12];
    const float* cb2 = (const float*)d_in[13];
    const float* cw3 = (const float*)d_in[14];
    const float* cb3 = (const float*)d_in[15];
    const float* lw0 = (const float*)d_in[16];
    const float* lb0 = (const float*)d_in[17];
    const float* lw1 = (const float*)d_in[18];
    const float* lb1 = (const float*)d_in[19];
    const float* lw2 = (const float*)d_in[20];
    const float* lb2 = (const float*)d_in[21];
    const float* lw3 = (const float*)d_in[22];
    const float* lb3 = (const float*)d_in[23];

    int n = in_sizes[0];

    reduce_scalars_kernel<<<RED_BLOCKS, RED_THREADS>>>(
        grad, s0, s1, n, loss_cur, loss_old, iter_p,
        lw0, lb0, lw1, lb1, lw2, lb2, lw3, lb3);
    main_kernel<<<MAIN_BLOCKS, MAIN_THREADS>>>(grad, s0, s1, gp, ex,
                                               cw0, cb0, cw1, cb1, cw2, cb2,
                                               cw3, cb3, (float*)d_out, n);
}

// round 7
// speedup vs baseline: 1.3894x; 1.3894x over previous
#include <cuda_runtime.h>
#include <math.h>

// Learned optimizer step — designed for a 32-register/thread compile cap.
// All per-element MLP activations are staged in SHARED memory
// (sact[buf][channel][tid], conflict-free); registers hold only 10
// half-layer accumulators + transients. No local arrays, no spill.
//
// Inputs (metadata order):
// 0 grad[N] 1 state0[N] 2 state1[N] 3 loss_cur[1] 4 loss_old[1] 5 iteration[1]
// 6 gradient_param[N] 7 extrapolation[N]
// 8 cw0[20x4] 9 cb0[20] 10 cw1[20x20] 11 cb1[20] 12 cw2[20x20] 13 cb2[20]
// 14 cw3[1x20] 15 cb3[1]
// 16 lw0[30x6] 17 lb0[30] 18 lw1[20x30] 19 lb1[20] 20 lw2[10x20] 21 lb2[10]
// 22 lw3[4x10] 23 lb3[4]
// Output: float32 [N]

#define RED_BLOCKS 1024
#define RED_THREADS 256
#define MAIN_THREADS 128
#define MAIN_BLOCKS 8192

__device__ float4 g_part[RED_BLOCKS];
__device__ unsigned int g_ticket = 0;
__device__ float g_coeff0, g_coeff1, g_coeff2, g_coeff3;
__device__ float g_inv_gn;
__device__ float g_inv_dn;
__device__ float g_fscale;

// ---------------------------------------------------------------------------
// Kernel A (fused): block partial reductions + last-block finalize
// ---------------------------------------------------------------------------
__global__ void reduce_scalars_kernel(
    const float* __restrict__ grad, const float* __restrict__ s0,
    const float* __restrict__ s1, int n,
    const float* __restrict__ loss_cur, const float* __restrict__ loss_old,
    const int* __restrict__ iter_p,
    const float* __restrict__ lw0, const float* __restrict__ lb0,
    const float* __restrict__ lw1, const float* __restrict__ lb1,
    const float* __restrict__ lw2, const float* __restrict__ lb2,
    const float* __restrict__ lw3, const float* __restrict__ lb3) {
    __shared__ float4 sh[RED_THREADS / 32];
    __shared__ int s_last;
    __shared__ float sfeat[6];
    __shared__ float sh0[30];
    __shared__ float sh1[20];
    __shared__ float sh2[10];

    int tid = threadIdx.x;
    int n4 = n >> 2;
    float sg2 = 0.f, sd2 = 0.f, sgd = 0.f, amax = 0.f;
    for (int i = blockIdx.x * blockDim.x + tid; i < n4;
         i += gridDim.x * blockDim.x) {
        float4 g = ((const float4*)grad)[i];
        float4 a = ((const float4*)s0)[i];
        float4 b = ((const float4*)s1)[i];
        float dx = b.x - a.x, dy = b.y - a.y, dz = b.z - a.z, dw = b.w - a.w;
        sg2 += g.x * g.x + g.y * g.y + g.z * g.z + g.w * g.w;
        sd2 += dx * dx + dy * dy + dz * dz + dw * dw;
        sgd += g.x * dx + g.y * dy + g.z * dz + g.w * dw;
        amax = fmaxf(amax, fmaxf(fmaxf(fabsf(g.x), fabsf(g.y)),
                                 fmaxf(fabsf(g.z), fabsf(g.w))));
    }
    #pragma unroll
    for (int off = 16; off; off >>= 1) {
        sg2 += __shfl_down_sync(0xffffffffu, sg2, off);
        sd2 += __shfl_down_sync(0xffffffffu, sd2, off);
        sgd += __shfl_down_sync(0xffffffffu, sgd, off);
        amax = fmaxf(amax, __shfl_down_sync(0xffffffffu, amax, off));
    }
    int lane = tid & 31, w = tid >> 5;
    if (!lane) sh[w] = make_float4(sg2, sd2, sgd, amax);
    __syncthreads();
    if (tid == 0) {
        float4 v = sh[0];
        #pragma unroll
        for (int i = 1; i < RED_THREADS / 32; i++) {
            float4 q = sh[i];
            v.x += q.x; v.y += q.y; v.z += q.z; v.w = fmaxf(v.w, q.w);
        }
        g_part[blockIdx.x] = v;
        __threadfence();
        unsigned int old = atomicInc(&g_ticket, RED_BLOCKS - 1);
        s_last = (old == RED_BLOCKS - 1);
    }
    __syncthreads();
    if (!s_last) return;

    // last block: combine partials in fixed order
    sg2 = 0.f; sd2 = 0.f; sgd = 0.f; amax = 0.f;
    for (int i = tid; i < RED_BLOCKS; i += RED_THREADS) {
        float4 p = g_part[i];
        sg2 += p.x; sd2 += p.y; sgd += p.z; amax = fmaxf(amax, p.w);
    }
    #pragma unroll
    for (int off = 16; off; off >>= 1) {
        sg2 += __shfl_down_sync(0xffffffffu, sg2, off);
        sd2 += __shfl_down_sync(0xffffffffu, sd2, off);
        sgd += __shfl_down_sync(0xffffffffu, sgd, off);
        amax = fmaxf(amax, __shfl_down_sync(0xffffffffu, amax, off));
    }
    __syncthreads();
    if (!lane) sh[w] = make_float4(sg2, sd2, sgd, amax);
    __syncthreads();

    if (tid == 0) {
        float4 v = sh[0];
        #pragma unroll
        for (int i = 1; i < RED_THREADS / 32; i++) {
            float4 q = sh[i];
            v.x += q.x; v.y += q.y; v.z += q.z; v.w = fmaxf(v.w, q.w);
        }
        float gn = sqrtf(v.x);
        float dn = sqrtf(v.y);
        float inv_gn = (gn > 1e-10f) ? (1.0f / gn) : 1.0f;
        float inv_dn = (dn > 1e-10f) ? (1.0f / dn) : 1.0f;
        float it = (float)iter_p[0];
        sfeat[0] = log1pf(gn);
        sfeat[1] = log1pf(dn);
        sfeat[2] = v.z * inv_gn * inv_dn;
        sfeat[3] = v.w * inv_gn;
        sfeat[4] = it;
        sfeat[5] = logf(loss_cur[0]) - logf(loss_old[0]);
        g_inv_gn = inv_gn;
        g_inv_dn = inv_dn;
        g_fscale = 1.0f / sqrtf(1.0f + it);
    }
    __syncthreads();

    if (tid < 30) {
        float a = lb0[tid];
        #pragma unroll
        for (int f = 0; f < 6; f++) a = fmaf(lw0[tid * 6 + f], sfeat[f], a);
        sh0[tid] = fmaxf(a, 0.0f);
    }
    __syncthreads();
    if (tid < 20) {
        float a = lb1[tid];
        #pragma unroll
        for (int c = 0; c < 30; c++) a = fmaf(lw1[tid * 30 + c], sh0[c], a);
        sh1[tid] = fmaxf(a, 0.0f);
    }
    __syncthreads();
    if (tid < 10) {
        float a = lb2[tid];
        #pragma unroll
        for (int c = 0; c < 20; c++) a = fmaf(lw2[tid * 20 + c], sh1[c], a);
        sh2[tid] = fmaxf(a, 0.0f);
    }
    __syncthreads();
    if (tid < 4) {
        float a = lb3[tid];
        #pragma unroll
        for (int c = 0; c < 10; c++) a = fmaf(lw3[tid * 10 + c], sh2[c], a);
        if (tid == 0) g_coeff0 = a;
        if (tid == 1) g_coeff1 = a;
        if (tid == 2) g_coeff2 = a;
        if (tid == 3) g_coeff3 = a;
    }
}

// ---------------------------------------------------------------------------
// Kernel B: per-element MLP 4->20->20->20->1.
// Activations in shared (per-thread column), 10 accumulators in registers.
// Weight rows padded to 12 floats: 3 aligned LDS.128 per input channel.
// ---------------------------------------------------------------------------

// acc += weight-row[C] (10 outs) * sact[BUF][C][tid]
#define WACC(SW, C, BUF) { \
    float hv_ = sact[BUF][C][tid]; \
    const float4* r_ = (const float4*)&(SW)[C][0]; \
    float4 q0 = r_[0], q1 = r_[1], q2 = r_[2]; \
    a0 = fmaf(q0.x, hv_, a0); a1 = fmaf(q0.y, hv_, a1); \
    a2 = fmaf(q0.z, hv_, a2); a3 = fmaf(q0.w, hv_, a3); \
    a4 = fmaf(q1.x, hv_, a4); a5 = fmaf(q1.y, hv_, a5); \
    a6 = fmaf(q1.z, hv_, a6); a7 = fmaf(q1.w, hv_, a7); \
    a8 = fmaf(q2.x, hv_, a8); a9 = fmaf(q2.y, hv_, a9); }

#define BIAS10(SB) { \
    const float4* b_ = (const float4*)(SB); \
    float4 q0 = b_[0], q1 = b_[1], q2 = b_[2]; \
    a0 = q0.x; a1 = q0.y; a2 = q0.z; a3 = q0.w; \
    a4 = q1.x; a5 = q1.y; a6 = q1.z; a7 = q1.w; \
    a8 = q2.x; a9 = q2.y; }

#define STREL(BUF, BASE) \
    sact[BUF][(BASE) + 0][tid] = fmaxf(a0, 0.f); \
    sact[BUF][(BASE) + 1][tid] = fmaxf(a1, 0.f); \
    sact[BUF][(BASE) + 2][tid] = fmaxf(a2, 0.f); \
    sact[BUF][(BASE) + 3][tid] = fmaxf(a3, 0.f); \
    sact[BUF][(BASE) + 4][tid] = fmaxf(a4, 0.f); \
    sact[BUF][(BASE) + 5][tid] = fmaxf(a5, 0.f); \
    sact[BUF][(BASE) + 6][tid] = fmaxf(a6, 0.f); \
    sact[BUF][(BASE) + 7][tid] = fmaxf(a7, 0.f); \
    sact[BUF][(BASE) + 8][tid] = fmaxf(a8, 0.f); \
    sact[BUF][(BASE) + 9][tid] = fmaxf(a9, 0.f);

#define HALF20(SW, SB, BUF) \
    BIAS10(SB) \
    WACC(SW, 0, BUF)  WACC(SW, 1, BUF)  WACC(SW, 2, BUF)  WACC(SW, 3, BUF) \
    WACC(SW, 4, BUF)  WACC(SW, 5, BUF)  WACC(SW, 6, BUF)  WACC(SW, 7, BUF) \
    WACC(SW, 8, BUF)  WACC(SW, 9, BUF)  WACC(SW, 10, BUF) WACC(SW, 11, BUF) \
    WACC(SW, 12, BUF) WACC(SW, 13, BUF) WACC(SW, 14, BUF) WACC(SW, 15, BUF) \
    WACC(SW, 16, BUF) WACC(SW, 17, BUF) WACC(SW, 18, BUF) WACC(SW, 19, BUF)

#define HALF4(SW, SB, BUF) \
    BIAS10(SB) \
    WACC(SW, 0, BUF) WACC(SW, 1, BUF) WACC(SW, 2, BUF) WACC(SW, 3, BUF)

__global__ void __launch_bounds__(MAIN_THREADS) main_kernel(
    const float* __restrict__ grad, const float* __restrict__ s0,
    const float* __restrict__ s1, const float* __restrict__ gp,
    const float* __restrict__ ex,
    const float* __restrict__ cw0, const float* __restrict__ cb0,
    const float* __restrict__ cw1, const float* __restrict__ cb1,
    const float* __restrict__ cw2, const float* __restrict__ cb2,
    const float* __restrict__ cw3, const float* __restrict__ cb3,
    float* __restrict__ out, int n) {
    // activations: [buffer][channel][thread], stride-1 in tid -> conflict-free
    __shared__ float sact[2][20][MAIN_THREADS];
    // weights: half-layer tiles, row = input channel, padded to 12 floats
    __shared__ __align__(16) float sw0a[4][12],  sw0b[4][12];
    __shared__ __align__(16) float sw1a[20][12], sw1b[20][12];
    __shared__ __align__(16) float sw2a[20][12], sw2b[20][12];
    __shared__ __align__(16) float sw3[20];
    __shared__ __align__(16) float sb0a[12], sb0b[12];
    __shared__ __align__(16) float sb1a[12], sb1b[12];
    __shared__ __align__(16) float sb2a[12], sb2b[12];
    __shared__ float sb3f;

    int tid = threadIdx.x;

    // ---- stage weights (transposed, halved, padded; coeff/fscale folded) ----
    if (tid < 48) {
        int c = tid / 12, j = tid % 12;
        float c0 = g_coeff0, c1 = g_coeff1, c2 = g_coeff2, c3 = g_coeff3;
        float cf = (c == 0) ? c0 : (c == 1) ? c1 : (c == 2) ? c2 : c3;
        sw0a[c][j] = (j < 10) ? cw0[j * 4 + c] * cf : 0.f;
        sw0b[c][j] = (j < 10) ? cw0[(j + 10) * 4 + c] * cf : 0.f;
    }
    for (int k = tid; k < 240; k += MAIN_THREADS) {
        int c = k / 12, j = k % 12;
        sw1a[c][j] = (j < 10) ? cw1[j * 20 + c] : 0.f;
        sw1b[c][j] = (j < 10) ? cw1[(j + 10) * 20 + c] : 0.f;
        sw2a[c][j] = (j < 10) ? cw2[j * 20 + c] : 0.f;
        sw2b[c][j] = (j < 10) ? cw2[(j + 10) * 20 + c] : 0.f;
    }
    if (tid < 12) {
        sb0a[tid] = (tid < 10) ? cb0[tid] : 0.f;
        sb0b[tid] = (tid < 10) ? cb0[tid + 10] : 0.f;
        sb1a[tid] = (tid < 10) ? cb1[tid] : 0.f;
        sb1b[tid] = (tid < 10) ? cb1[tid + 10] : 0.f;
        sb2a[tid] = (tid < 10) ? cb2[tid] : 0.f;
        sb2b[tid] = (tid < 10) ? cb2[tid + 10] : 0.f;
    }
    if (tid < 20) sw3[tid] = cw3[tid] * g_fscale;
    if (tid == 0) sb3f = cb3[0] * g_fscale;
    __syncthreads();

    float inv_gn = g_inv_gn, inv_dn = g_inv_dn;

    int stride = gridDim.x * MAIN_THREADS;
    for (int i = blockIdx.x * MAIN_THREADS + tid; i < n; i += stride) {
        // ---- inputs -> 4 channels in buf0 ----
        {
            float gx = grad[i] * inv_gn;
            float dv = (s1[i] - s0[i]) * inv_dn;
            sact[0][0][tid] = gp[i] * gx;   // gradient_param * g
            sact[0][1][tid] = ex[i] * dv;   // extrapolation * d
            sact[0][2][tid] = gx;           // g
            sact[0][3][tid] = dv;           // d
        }

        float a0, a1, a2, a3, a4, a5, a6, a7, a8, a9;

        // ---- layer 0: 4 -> 20 (buf0 -> buf1) ----
        HALF4(sw0a, sb0a, 0)
        STREL(1, 0)
        HALF4(sw0b, sb0b, 0)
        STREL(1, 10)

        // ---- layer 1: 20 -> 20 (buf1 -> buf0) ----
        HALF20(sw1a, sb1a, 1)
        STREL(0, 0)
        HALF20(sw1b, sb1b, 1)
        STREL(0, 10)

        // ---- layer 2: 20 -> 20 (buf0 -> buf1) ----
        HALF20(sw2a, sb2a, 0)
        STREL(1, 0)
        HALF20(sw2b, sb2b, 0)
        STREL(1, 10)

        // ---- layer 3: 20 -> 1 (fscale folded into sw3/sb3) ----
        float acc = sb3f;
        {
            const float4* r_ = (const float4*)sw3;
            float4 q0 = r_[0], q1 = r_[1], q2 = r_[2], q3 = r_[3], q4 = r_[4];
            acc = fmaf(q0.x, sact[1][0][tid], acc);
            acc = fmaf(q0.y, sact[1][1][tid], acc);
            acc = fmaf(q0.z, sact[1][2][tid], acc);
            acc = fmaf(q0.w, sact[1][3][tid], acc);
            acc = fmaf(q1.x, sact[1][4][tid], acc);
            acc = fmaf(q1.y, sact[1][5][tid], acc);
            acc = fmaf(q1.z, sact[1][6][tid], acc);
            acc = fmaf(q1.w, sact[1][7][tid], acc);
            acc = fmaf(q2.x, sact[1][8][tid], acc);
            acc = fmaf(q2.y, sact[1][9][tid], acc);
            acc = fmaf(q2.z, sact[1][10][tid], acc);
            acc = fmaf(q2.w, sact[1][11][tid], acc);
            acc = fmaf(q3.x, sact[1][12][tid], acc);
            acc = fmaf(q3.y, sact[1][13][tid], acc);
            acc = fmaf(q3.z, sact[1][14][tid], acc);
            acc = fmaf(q3.w, sact[1][15][tid], acc);
            acc = fmaf(q4.x, sact[1][16][tid], acc);
            acc = fmaf(q4.y, sact[1][17][tid], acc);
            acc = fmaf(q4.z, sact[1][18][tid], acc);
            acc = fmaf(q4.w, sact[1][19][tid], acc);
        }
        out[i] = s1[i] + acc;
    }
}

// ---------------------------------------------------------------------------
extern "C" void kernel_launch(void* const* d_in, const int* in_sizes, int n_in,
                              void* d_out, int out_size) {
    const float* grad = (const float*)d_in[0];
    const float* s0   = (const float*)d_in[1];
    const float* s1   = (const float*)d_in[2];
    const float* loss_cur = (const float*)d_in[3];
    const float* loss_old = (const float*)d_in[4];
    const int*   iter_p   = (const int*)d_in[5];
    const float* gp = (const float*)d_in[6];
    const float* ex = (const float*)d_in[7];
    const float* cw0 = (const float*)d_in[8];
    const float* cb0 = (const float*)d_in[9];
    const float* cw1 = (const float*)d_in[10];
    const float* cb1 = (const float*)d_in[11];
    const float* cw2 = (const float*)d_in[12];
    const float* cb2 = (const float*)d_in[13];
    const float* cw3 = (const float*)d_in[14];
    const float* cb3 = (const float*)d_in[15];
    const float* lw0 = (const float*)d_in[16];
    const float* lb0 = (const float*)d_in[17];
    const float* lw1 = (const float*)d_in[18];
    const float* lb1 = (const float*)d_in[19];
    const float* lw2 = (const float*)d_in[20];
    const float* lb2 = (const float*)d_in[21];
    const float* lw3 = (const float*)d_in[22];
    const float* lb3 = (const float*)d_in[23];

    int n = in_sizes[0];

    reduce_scalars_kernel<<<RED_BLOCKS, RED_THREADS>>>(
        grad, s0, s1, n, loss_cur, loss_old, iter_p,
        lw0, lb0, lw1, lb1, lw2, lb2, lw3, lb3);
    main_kernel<<<MAIN_BLOCKS, MAIN_THREADS>>>(grad, s0, s1, gp, ex,
                                               cw0, cb0, cw1, cb1, cw2, cb2,
                                               cw3, cb3, (float*)d_out, n);
}

// round 8
// speedup vs baseline: 17.0722x; 12.2875x over previous
#include <cuda_runtime.h>
#include <math.h>

// Learned optimizer step. Inputs (metadata order):
// 0 grad[N] 1 state0[N] 2 state1[N] 3 loss_cur[1] 4 loss_old[1] 5 iteration[1]
// 6 gradient_param[N] 7 extrapolation[N]
// 8 cw0[20x4] 9 cb0[20] 10 cw1[20x20] 11 cb1[20] 12 cw2[20x20] 13 cb2[20]
// 14 cw3[1x20] 15 cb3[1]
// 16 lw0[30x6] 17 lb0[30] 18 lw1[20x30] 19 lb1[20] 20 lw2[10x20] 21 lb2[10]
// 22 lw3[4x10] 23 lb3[4]
// Output: float32 [N]
//
// Main kernel: activations in REGISTERS, 2 elements/thread (independent u/v
// chains), weights in shared (12-float padded rows, 3 aligned LDS.128 per
// input channel, amortized over both elements). __launch_bounds__(128, 2)
// gives ptxas a 256-reg budget — defeats the occupancy heuristic that
// previously squeezed this body to 32 regs and spilled it.

#define RED_BLOCKS 1024
#define RED_THREADS 256
#define MAIN_THREADS 128

__device__ float4 g_part[RED_BLOCKS];
__device__ unsigned int g_ticket = 0;
__device__ float g_coeff0, g_coeff1, g_coeff2, g_coeff3;
__device__ float g_inv_gn;
__device__ float g_inv_dn;
__device__ float g_fscale;

// ---------------------------------------------------------------------------
// Kernel A (fused): block partial reductions + last-block finalize
// ---------------------------------------------------------------------------
__global__ void reduce_scalars_kernel(
    const float* __restrict__ grad, const float* __restrict__ s0,
    const float* __restrict__ s1, int n,
    const float* __restrict__ loss_cur, const float* __restrict__ loss_old,
    const int* __restrict__ iter_p,
    const float* __restrict__ lw0, const float* __restrict__ lb0,
    const float* __restrict__ lw1, const float* __restrict__ lb1,
    const float* __restrict__ lw2, const float* __restrict__ lb2,
    const float* __restrict__ lw3, const float* __restrict__ lb3) {
    __shared__ float4 sh[RED_THREADS / 32];
    __shared__ int s_last;
    __shared__ float sfeat[6];
    __shared__ float sh0[30];
    __shared__ float sh1[20];
    __shared__ float sh2[10];

    int tid = threadIdx.x;
    int n4 = n >> 2;
    float sg2 = 0.f, sd2 = 0.f, sgd = 0.f, amax = 0.f;
    for (int i = blockIdx.x * blockDim.x + tid; i < n4;
         i += gridDim.x * blockDim.x) {
        float4 g = ((const float4*)grad)[i];
        float4 a = ((const float4*)s0)[i];
        float4 b = ((const float4*)s1)[i];
        float dx = b.x - a.x, dy = b.y - a.y, dz = b.z - a.z, dw = b.w - a.w;
        sg2 += g.x * g.x + g.y * g.y + g.z * g.z + g.w * g.w;
        sd2 += dx * dx + dy * dy + dz * dz + dw * dw;
        sgd += g.x * dx + g.y * dy + g.z * dz + g.w * dw;
        amax = fmaxf(amax, fmaxf(fmaxf(fabsf(g.x), fabsf(g.y)),
                                 fmaxf(fabsf(g.z), fabsf(g.w))));
    }
    #pragma unroll
    for (int off = 16; off; off >>= 1) {
        sg2 += __shfl_down_sync(0xffffffffu, sg2, off);
        sd2 += __shfl_down_sync(0xffffffffu, sd2, off);
        sgd += __shfl_down_sync(0xffffffffu, sgd, off);
        amax = fmaxf(amax, __shfl_down_sync(0xffffffffu, amax, off));
    }
    int lane = tid & 31, w = tid >> 5;
    if (!lane) sh[w] = make_float4(sg2, sd2, sgd, amax);
    __syncthreads();
    if (tid == 0) {
        float4 v = sh[0];
        #pragma unroll
        for (int i = 1; i < RED_THREADS / 32; i++) {
            float4 q = sh[i];
            v.x += q.x; v.y += q.y; v.z += q.z; v.w = fmaxf(v.w, q.w);
        }
        g_part[blockIdx.x] = v;
        __threadfence();
        unsigned int old = atomicInc(&g_ticket, RED_BLOCKS - 1);
        s_last = (old == RED_BLOCKS - 1);
    }
    __syncthreads();
    if (!s_last) return;

    sg2 = 0.f; sd2 = 0.f; sgd = 0.f; amax = 0.f;
    for (int i = tid; i < RED_BLOCKS; i += RED_THREADS) {
        float4 p = g_part[i];
        sg2 += p.x; sd2 += p.y; sgd += p.z; amax = fmaxf(amax, p.w);
    }
    #pragma unroll
    for (int off = 16; off; off >>= 1) {
        sg2 += __shfl_down_sync(0xffffffffu, sg2, off);
        sd2 += __shfl_down_sync(0xffffffffu, sd2, off);
        sgd += __shfl_down_sync(0xffffffffu, sgd, off);
        amax = fmaxf(amax, __shfl_down_sync(0xffffffffu, amax, off));
    }
    __syncthreads();
    if (!lane) sh[w] = make_float4(sg2, sd2, sgd, amax);
    __syncthreads();

    if (tid == 0) {
        float4 v = sh[0];
        #pragma unroll
        for (int i = 1; i < RED_THREADS / 32; i++) {
            float4 q = sh[i];
            v.x += q.x; v.y += q.y; v.z += q.z; v.w = fmaxf(v.w, q.w);
        }
        float gn = sqrtf(v.x);
        float dn = sqrtf(v.y);
        float inv_gn = (gn > 1e-10f) ? (1.0f / gn) : 1.0f;
        float inv_dn = (dn > 1e-10f) ? (1.0f / dn) : 1.0f;
        float it = (float)iter_p[0];
        sfeat[0] = log1pf(gn);
        sfeat[1] = log1pf(dn);
        sfeat[2] = v.z * inv_gn * inv_dn;
        sfeat[3] = v.w * inv_gn;
        sfeat[4] = it;
        sfeat[5] = logf(loss_cur[0]) - logf(loss_old[0]);
        g_inv_gn = inv_gn;
        g_inv_dn = inv_dn;
        g_fscale = 1.0f / sqrtf(1.0f + it);
    }
    __syncthreads();

    if (tid < 30) {
        float a = lb0[tid];
        #pragma unroll
        for (int f = 0; f < 6; f++) a = fmaf(lw0[tid * 6 + f], sfeat[f], a);
        sh0[tid] = fmaxf(a, 0.0f);
    }
    __syncthreads();
    if (tid < 20) {
        float a = lb1[tid];
        #pragma unroll
        for (int c = 0; c < 30; c++) a = fmaf(lw1[tid * 30 + c], sh0[c], a);
        sh1[tid] = fmaxf(a, 0.0f);
    }
    __syncthreads();
    if (tid < 10) {
        float a = lb2[tid];
        #pragma unroll
        for (int c = 0; c < 20; c++) a = fmaf(lw2[tid * 20 + c], sh1[c], a);
        sh2[tid] = fmaxf(a, 0.0f);
    }
    __syncthreads();
    if (tid < 4) {
        float a = lb3[tid];
        #pragma unroll
        for (int c = 0; c < 10; c++) a = fmaf(lw3[tid * 10 + c], sh2[c], a);
        if (tid == 0) g_coeff0 = a;
        if (tid == 1) g_coeff1 = a;
        if (tid == 2) g_coeff2 = a;
        if (tid == 3) g_coeff3 = a;
    }
}

// ---------------------------------------------------------------------------
// Kernel B: per-element MLP 4->20->20->20->1, 2 elements/thread (u, v),
// activations in registers, half-layer (10-output) accumulation.
// ---------------------------------------------------------------------------

// au0..9 / av0..9 += weight-row (10 outs) * {HU, HV}: 3 quad LDS, 20 FFMA
#define ACC2H(ROWPTR, HU, HV) { \
    const float4* r_ = (const float4*)(ROWPTR); \
    float4 q0 = r_[0], q1 = r_[1], q2 = r_[2]; \
    au0 = fmaf(q0.x, (HU), au0); av0 = fmaf(q0.x, (HV), av0); \
    au1 = fmaf(q0.y, (HU), au1); av1 = fmaf(q0.y, (HV), av1); \
    au2 = fmaf(q0.z, (HU), au2); av2 = fmaf(q0.z, (HV), av2); \
    au3 = fmaf(q0.w, (HU), au3); av3 = fmaf(q0.w, (HV), av3); \
    au4 = fmaf(q1.x, (HU), au4); av4 = fmaf(q1.x, (HV), av4); \
    au5 = fmaf(q1.y, (HU), au5); av5 = fmaf(q1.y, (HV), av5); \
    au6 = fmaf(q1.z, (HU), au6); av6 = fmaf(q1.z, (HV), av6); \
    au7 = fmaf(q1.w, (HU), au7); av7 = fmaf(q1.w, (HV), av7); \
    au8 = fmaf(q2.x, (HU), au8); av8 = fmaf(q2.x, (HV), av8); \
    au9 = fmaf(q2.y, (HU), au9); av9 = fmaf(q2.y, (HV), av9); }

#define BIASH(SB) { \
    const float4* b_ = (const float4*)(SB); \
    float4 q0 = b_[0], q1 = b_[1], q2 = b_[2]; \
    au0 = q0.x; au1 = q0.y; au2 = q0.z; au3 = q0.w; \
    au4 = q1.x; au5 = q1.y; au6 = q1.z; au7 = q1.w; \
    au8 = q2.x; au9 = q2.y; \
    av0 = au0; av1 = au1; av2 = au2; av3 = au3; av4 = au4; \
    av5 = au5; av6 = au6; av7 = au7; av8 = au8; av9 = au9; }

#define RELU_A(P) \
    P##u0 = fmaxf(au0, 0.f); P##u1 = fmaxf(au1, 0.f); P##u2 = fmaxf(au2, 0.f); \
    P##u3 = fmaxf(au3, 0.f); P##u4 = fmaxf(au4, 0.f); P##u5 = fmaxf(au5, 0.f); \
    P##u6 = fmaxf(au6, 0.f); P##u7 = fmaxf(au7, 0.f); P##u8 = fmaxf(au8, 0.f); \
    P##u9 = fmaxf(au9, 0.f); \
    P##v0 = fmaxf(av0, 0.f); P##v1 = fmaxf(av1, 0.f); P##v2 = fmaxf(av2, 0.f); \
    P##v3 = fmaxf(av3, 0.f); P##v4 = fmaxf(av4, 0.f); P##v5 = fmaxf(av5, 0.f); \
    P##v6 = fmaxf(av6, 0.f); P##v7 = fmaxf(av7, 0.f); P##v8 = fmaxf(av8, 0.f); \
    P##v9 = fmaxf(av9, 0.f);

#define RELU_B(P) \
    P##u10 = fmaxf(au0, 0.f); P##u11 = fmaxf(au1, 0.f); P##u12 = fmaxf(au2, 0.f); \
    P##u13 = fmaxf(au3, 0.f); P##u14 = fmaxf(au4, 0.f); P##u15 = fmaxf(au5, 0.f); \
    P##u16 = fmaxf(au6, 0.f); P##u17 = fmaxf(au7, 0.f); P##u18 = fmaxf(au8, 0.f); \
    P##u19 = fmaxf(au9, 0.f); \
    P##v10 = fmaxf(av0, 0.f); P##v11 = fmaxf(av1, 0.f); P##v12 = fmaxf(av2, 0.f); \
    P##v13 = fmaxf(av3, 0.f); P##v14 = fmaxf(av4, 0.f); P##v15 = fmaxf(av5, 0.f); \
    P##v16 = fmaxf(av6, 0.f); P##v17 = fmaxf(av7, 0.f); P##v18 = fmaxf(av8, 0.f); \
    P##v19 = fmaxf(av9, 0.f);

#define HALF20(SW, SB, IP) \
    BIASH(SB) \
    ACC2H(&(SW)[0][0],  IP##u0,  IP##v0)  ACC2H(&(SW)[1][0],  IP##u1,  IP##v1) \
    ACC2H(&(SW)[2][0],  IP##u2,  IP##v2)  ACC2H(&(SW)[3][0],  IP##u3,  IP##v3) \
    ACC2H(&(SW)[4][0],  IP##u4,  IP##v4)  ACC2H(&(SW)[5][0],  IP##u5,  IP##v5) \
    ACC2H(&(SW)[6][0],  IP##u6,  IP##v6)  ACC2H(&(SW)[7][0],  IP##u7,  IP##v7) \
    ACC2H(&(SW)[8][0],  IP##u8,  IP##v8)  ACC2H(&(SW)[9][0],  IP##u9,  IP##v9) \
    ACC2H(&(SW)[10][0], IP##u10, IP##v10) ACC2H(&(SW)[11][0], IP##u11, IP##v11) \
    ACC2H(&(SW)[12][0], IP##u12, IP##v12) ACC2H(&(SW)[13][0], IP##u13, IP##v13) \
    ACC2H(&(SW)[14][0], IP##u14, IP##v14) ACC2H(&(SW)[15][0], IP##u15, IP##v15) \
    ACC2H(&(SW)[16][0], IP##u16, IP##v16) ACC2H(&(SW)[17][0], IP##u17, IP##v17) \
    ACC2H(&(SW)[18][0], IP##u18, IP##v18) ACC2H(&(SW)[19][0], IP##u19, IP##v19)

#define DECL20(P) \
    float P##u0, P##u1, P##u2, P##u3, P##u4, P##u5, P##u6, P##u7, P##u8, P##u9, \
          P##u10, P##u11, P##u12, P##u13, P##u14, P##u15, P##u16, P##u17, P##u18, P##u19; \
    float P##v0, P##v1, P##v2, P##v3, P##v4, P##v5, P##v6, P##v7, P##v8, P##v9, \
          P##v10, P##v11, P##v12, P##v13, P##v14, P##v15, P##v16, P##v17, P##v18, P##v19;

__global__ void __launch_bounds__(MAIN_THREADS, 2) main_kernel(
    const float* __restrict__ grad, const float* __restrict__ s0,
    const float* __restrict__ s1, const float* __restrict__ gp,
    const float* __restrict__ ex,
    const float* __restrict__ cw0, const float* __restrict__ cb0,
    const float* __restrict__ cw1, const float* __restrict__ cb1,
    const float* __restrict__ cw2, const float* __restrict__ cb2,
    const float* __restrict__ cw3, const float* __restrict__ cb3,
    float* __restrict__ out, int n) {
    __shared__ __align__(16) float sw0a[4][12],  sw0b[4][12];
    __shared__ __align__(16) float sw1a[20][12], sw1b[20][12];
    __shared__ __align__(16) float sw2a[20][12], sw2b[20][12];
    __shared__ __align__(16) float sw3[20];
    __shared__ __align__(16) float sb0a[12], sb0b[12];
    __shared__ __align__(16) float sb1a[12], sb1b[12];
    __shared__ __align__(16) float sb2a[12], sb2b[12];
    __shared__ float sb3f;

    int tid = threadIdx.x;

    // ---- stage weights (transposed, halved, padded; coeff/fscale folded) ----
    if (tid < 48) {
        int c = tid / 12, j = tid % 12;
        float c0 = g_coeff0, c1 = g_coeff1, c2 = g_coeff2, c3 = g_coeff3;
        float cf = (c == 0) ? c0 : (c == 1) ? c1 : (c == 2) ? c2 : c3;
        sw0a[c][j] = (j < 10) ? cw0[j * 4 + c] * cf : 0.f;
        sw0b[c][j] = (j < 10) ? cw0[(j + 10) * 4 + c] * cf : 0.f;
    }
    for (int k = tid; k < 240; k += MAIN_THREADS) {
        int c = k / 12, j = k % 12;
        sw1a[c][j] = (j < 10) ? cw1[j * 20 + c] : 0.f;
        sw1b[c][j] = (j < 10) ? cw1[(j + 10) * 20 + c] : 0.f;
        sw2a[c][j] = (j < 10) ? cw2[j * 20 + c] : 0.f;
        sw2b[c][j] = (j < 10) ? cw2[(j + 10) * 20 + c] : 0.f;
    }
    if (tid < 12) {
        sb0a[tid] = (tid < 10) ? cb0[tid] : 0.f;
        sb0b[tid] = (tid < 10) ? cb0[tid + 10] : 0.f;
        sb1a[tid] = (tid < 10) ? cb1[tid] : 0.f;
        sb1b[tid] = (tid < 10) ? cb1[tid + 10] : 0.f;
        sb2a[tid] = (tid < 10) ? cb2[tid] : 0.f;
        sb2b[tid] = (tid < 10) ? cb2[tid + 10] : 0.f;
    }
    if (tid < 20) sw3[tid] = cw3[tid] * g_fscale;
    if (tid == 0) sb3f = cb3[0] * g_fscale;
    __syncthreads();

    int p = blockIdx.x * MAIN_THREADS + tid;
    int npair = n >> 1;
    if (p >= npair) return;

    float inv_gn = g_inv_gn, inv_dn = g_inv_dn;

    float2 g2 = ((const float2*)grad)[p];
    float2 a2 = ((const float2*)s0)[p];
    float2 b2 = ((const float2*)s1)[p];
    float2 p2 = ((const float2*)gp)[p];
    float2 e2 = ((const float2*)ex)[p];

    float gxu = g2.x * inv_gn, gxv = g2.y * inv_gn;
    float dxu = (b2.x - a2.x) * inv_dn, dxv = (b2.y - a2.y) * inv_dn;
    float t0u = p2.x * gxu, t0v = p2.y * gxv;  // gradient_param * g
    float t1u = e2.x * dxu, t1v = e2.y * dxv;  // extrapolation * d

    float au0, au1, au2, au3, au4, au5, au6, au7, au8, au9;
    float av0, av1, av2, av3, av4, av5, av6, av7, av8, av9;
    DECL20(h)
    DECL20(g)

    // ---- layer 0: 4 -> 20 (two halves) ----
    BIASH(sb0a)
    ACC2H(&sw0a[0][0], t0u, t0v) ACC2H(&sw0a[1][0], t1u, t1v)
    ACC2H(&sw0a[2][0], gxu, gxv) ACC2H(&sw0a[3][0], dxu, dxv)
    RELU_A(h)
    BIASH(sb0b)
    ACC2H(&sw0b[0][0], t0u, t0v) ACC2H(&sw0b[1][0], t1u, t1v)
    ACC2H(&sw0b[2][0], gxu, gxv) ACC2H(&sw0b[3][0], dxu, dxv)
    RELU_B(h)

    // ---- layer 1: 20 -> 20 (h -> g) ----
    HALF20(sw1a, sb1a, h)
    RELU_A(g)
    HALF20(sw1b, sb1b, h)
    RELU_B(g)

    // ---- layer 2: 20 -> 20 (g -> h) ----
    HALF20(sw2a, sb2a, g)
    RELU_A(h)
    HALF20(sw2b, sb2b, g)
    RELU_B(h)

    // ---- layer 3: 20 -> 1 (fscale folded) ----
    float accu = sb3f, accv = sb3f;
    {
        const float4* r_ = (const float4*)sw3;
        float4 q0 = r_[0], q1 = r_[1], q2 = r_[2], q3 = r_[3], q4 = r_[4];
        accu = fmaf(q0.x, hu0, accu);  accv = fmaf(q0.x, hv0, accv);
        accu = fmaf(q0.y, hu1, accu);  accv = fmaf(q0.y, hv1, accv);
        accu = fmaf(q0.z, hu2, accu);  accv = fmaf(q0.z, hv2, accv);
        accu = fmaf(q0.w, hu3, accu);  accv = fmaf(q0.w, hv3, accv);
        accu = fmaf(q1.x, hu4, accu);  accv = fmaf(q1.x, hv4, accv);
        accu = fmaf(q1.y, hu5, accu);  accv = fmaf(q1.y, hv5, accv);
        accu = fmaf(q1.z, hu6, accu);  accv = fmaf(q1.z, hv6, accv);
        accu = fmaf(q1.w, hu7, accu);  accv = fmaf(q1.w, hv7, accv);
        accu = fmaf(q2.x, hu8, accu);  accv = fmaf(q2.x, hv8, accv);
        accu = fmaf(q2.y, hu9, accu);  accv = fmaf(q2.y, hv9, accv);
        accu = fmaf(q2.z, hu10, accu); accv = fmaf(q2.z, hv10, accv);
        accu = fmaf(q2.w, hu11, accu); accv = fmaf(q2.w, hv11, accv);
        accu = fmaf(q3.x, hu12, accu); accv = fmaf(q3.x, hv12, accv);
        accu = fmaf(q3.y, hu13, accu); accv = fmaf(q3.y, hv13, accv);
        accu = fmaf(q3.z, hu14, accu); accv = fmaf(q3.z, hv14, accv);
        accu = fmaf(q3.w, hu15, accu); accv = fmaf(q3.w, hv15, accv);
        accu = fmaf(q4.x, hu16, accu); accv = fmaf(q4.x, hv16, accv);
        accu = fmaf(q4.y, hu17, accu); accv = fmaf(q4.y, hv17, accv);
        accu = fmaf(q4.z, hu18, accu); accv = fmaf(q4.z, hv18, accv);
        accu = fmaf(q4.w, hu19, accu); accv = fmaf(q4.w, hv19, accv);
    }
    float2 o2;
    o2.x = b2.x + accu;
    o2.y = b2.y + accv;
    ((float2*)out)[p] = o2;
}

// ---------------------------------------------------------------------------
extern "C" void kernel_launch(void* const* d_in, const int* in_sizes, int n_in,
                              void* d_out, int out_size) {
    const float* grad = (const float*)d_in[0];
    const float* s0   = (const float*)d_in[1];
    const float* s1   = (const float*)d_in[2];
    const float* loss_cur = (const float*)d_in[3];
    const float* loss_old = (const float*)d_in[4];
    const int*   iter_p   = (const int*)d_in[5];
    const float* gp = (const float*)d_in[6];
    const float* ex = (const float*)d_in[7];
    const float* cw0 = (const float*)d_in[8];
    const float* cb0 = (const float*)d_in[9];
    const float* cw1 = (const float*)d_in[10];
    const float* cb1 = (const float*)d_in[11];
    const float* cw2 = (const float*)d_in[12];
    const float* cb2 = (const float*)d_in[13];
    const float* cw3 = (const float*)d_in[14];
    const float* cb3 = (const float*)d_in[15];
    const float* lw0 = (const float*)d_in[16];
    const float* lb0 = (const float*)d_in[17];
    const float* lw1 = (const float*)d_in[18];
    const float* lb1 = (const float*)d_in[19];
    const float* lw2 = (const float*)d_in[20];
    const float* lb2 = (const float*)d_in[21];
    const float* lw3 = (const float*)d_in[22];
    const float* lb3 = (const float*)d_in[23];

    int n = in_sizes[0];
    int npair = n >> 1;
    int main_blocks = (npair + MAIN_THREADS - 1) / MAIN_THREADS;

    reduce_scalars_kernel<<<RED_BLOCKS, RED_THREADS>>>(
        grad, s0, s1, n, loss_cur, loss_old, iter_p,
        lw0, lb0, lw1, lb1, lw2, lb2, lw3, lb3);
    main_kernel<<<main_blocks, MAIN_THREADS>>>(grad, s0, s1, gp, ex,
                                               cw0, cb0, cw1, cb1, cw2, cb2,
                                               cw3, cb3, (float*)d_out, n);
}